// round 1
// baseline (speedup 1.0000x reference)
#include <cuda_runtime.h>
#include <math.h>

#define BB 8
#define NN 1024
#define DIM 192
#define HEADS 16
#define DHEAD 64
#define INNER 1024
#define TOK (BB*NN)       // 8192
#define QKVN (3*INNER)    // 3072

// Scratch (allocation-free rule: __device__ globals)
__device__ float g_h[TOK*DIM];
__device__ float g_qkv[(size_t)TOK*QKVN];
__device__ float g_attn[(size_t)TOK*INNER];

// ---------------------------------------------------------------------------
// LayerNorm + adaLN modulation: one warp per token (192 dims = 6/lane)
// ---------------------------------------------------------------------------
__global__ __launch_bounds__(256)
void ln_mod_kernel(const float* __restrict__ x,
                   const float* __restrict__ shift,
                   const float* __restrict__ scale,
                   const float* __restrict__ w,
                   const float* __restrict__ bpar) {
    int warp = threadIdx.x >> 5;
    int lane = threadIdx.x & 31;
    int t = blockIdx.x * 8 + warp;
    const float* xr = x + (size_t)t * DIM;
    float v[6];
    float s = 0.f;
#pragma unroll
    for (int q = 0; q < 6; q++) { v[q] = xr[lane + q*32]; s += v[q]; }
#pragma unroll
    for (int o = 16; o; o >>= 1) s += __shfl_xor_sync(0xffffffffu, s, o);
    float mu = s * (1.f/DIM);
    float vs = 0.f;
#pragma unroll
    for (int q = 0; q < 6; q++) { float d = v[q]-mu; vs += d*d; }
#pragma unroll
    for (int o = 16; o; o >>= 1) vs += __shfl_xor_sync(0xffffffffu, vs, o);
    float rstd = rsqrtf(vs*(1.f/DIM) + 1e-5f);
    int bi = t >> 10;   // token / N  -> batch index
#pragma unroll
    for (int q = 0; q < 6; q++) {
        int d = lane + q*32;
        float hn = (v[q]-mu)*rstd*w[d] + bpar[d];
        hn = hn * (1.f + scale[bi*DIM + d]) + shift[bi*DIM + d];
        g_h[(size_t)t*DIM + d] = hn;
    }
}

// ---------------------------------------------------------------------------
// Generic fp32 tiled GEMM: C[M,Nn] = A[M,K] @ Bm[K,Nn] (+ bias)
// BM=BN=64, BK=16, 256 threads, 4x4 microtile. M,Nn,K all multiples required.
// ---------------------------------------------------------------------------
__global__ __launch_bounds__(256)
void sgemm_kernel(const float* __restrict__ A, const float* __restrict__ Bm,
                  const float* __restrict__ bias, float* __restrict__ C,
                  int M, int Nn, int K) {
    __shared__ float As[16][64];
    __shared__ float Bs[16][64];
    int m0 = blockIdx.y * 64;
    int n0 = blockIdx.x * 64;
    int tid = threadIdx.x;
    int ty = tid >> 4, tx = tid & 15;
    float acc[4][4] = {};
    int lm = tid >> 2;            // A: row within tile
    int lk = (tid & 3) * 4;       // A: k quad
    int bk = tid >> 4;            // B: k row
    int bn = (tid & 15) * 4;      // B: n quad

    for (int kt = 0; kt < K; kt += 16) {
        float4 av = *(const float4*)&A[(size_t)(m0+lm)*K + kt + lk];
        As[lk+0][lm] = av.x; As[lk+1][lm] = av.y;
        As[lk+2][lm] = av.z; As[lk+3][lm] = av.w;
        *(float4*)&Bs[bk][bn] = *(const float4*)&Bm[(size_t)(kt+bk)*Nn + n0 + bn];
        __syncthreads();
#pragma unroll
        for (int kk = 0; kk < 16; kk++) {
            float4 a = *(float4*)&As[kk][ty*4];
            float4 b = *(float4*)&Bs[kk][tx*4];
            float ar[4] = {a.x, a.y, a.z, a.w};
            float br[4] = {b.x, b.y, b.z, b.w};
#pragma unroll
            for (int i = 0; i < 4; i++)
#pragma unroll
                for (int j = 0; j < 4; j++)
                    acc[i][j] = fmaf(ar[i], br[j], acc[i][j]);
        }
        __syncthreads();
    }
#pragma unroll
    for (int i = 0; i < 4; i++) {
        int row = m0 + ty*4 + i;
        float4 o = make_float4(acc[i][0], acc[i][1], acc[i][2], acc[i][3]);
        if (bias) {
            o.x += bias[n0 + tx*4 + 0];
            o.y += bias[n0 + tx*4 + 1];
            o.z += bias[n0 + tx*4 + 2];
            o.w += bias[n0 + tx*4 + 3];
        }
        *(float4*)&C[(size_t)row*Nn + n0 + tx*4] = o;
    }
}

// ---------------------------------------------------------------------------
// Flash attention, fp32. One block per (q-tile of 64, b*h).
// Q tile resident in smem; K/V streamed in 64-key tiles; online softmax.
// Row stats (m, l) live in registers, replicated across the 16 tx lanes via
// shfl reductions. P overwrites the K smem buffer between the two GEMMs.
// ---------------------------------------------------------------------------
#define KS_STRIDE 68   // padded to dodge bank conflicts on K reads
#define ATTN_SMEM_FLOATS (64*64 + 64*KS_STRIDE + 64*64)

__global__ __launch_bounds__(256)
void attn_kernel(const float* __restrict__ qkv, float* __restrict__ out) {
    extern __shared__ float sm[];
    float* Qs = sm;                    // 64 rows x 64 (stride 64)
    float* Ks = sm + 64*64;            // 64 keys x 64 (stride 68), reused as P
    float* Vs = Ks + 64*KS_STRIDE;     // 64 keys x 64 (stride 64)

    int qt = blockIdx.x;               // q tile: 0..15
    int bh = blockIdx.y;               // 0..127
    int b  = bh >> 4, h = bh & 15;
    int tid = threadIdx.x;
    int ty = tid >> 4, tx = tid & 15;

    const float* base = qkv + (size_t)b*NN*QKVN + h*DHEAD;

    // Load Q tile, folding the softmax scale (64^-0.5 = 0.125)
#pragma unroll
    for (int it = 0; it < 4; it++) {
        int idx = tid + it*256;
        int r = idx >> 4, c4 = (idx & 15) * 4;
        float4 v = *(const float4*)&base[(size_t)(qt*64 + r)*QKVN + c4];
        v.x *= 0.125f; v.y *= 0.125f; v.z *= 0.125f; v.w *= 0.125f;
        *(float4*)&Qs[r*64 + c4] = v;
    }

    float o[4][4] = {};
    float mi[4] = {-INFINITY, -INFINITY, -INFINITY, -INFINITY};
    float li[4] = {};

    for (int kt = 0; kt < 16; kt++) {
        __syncthreads();   // prior P/V reads complete before overwrite
#pragma unroll
        for (int it = 0; it < 4; it++) {
            int idx = tid + it*256;
            int r = idx >> 4, c4 = (idx & 15) * 4;
            const float* krow = &base[(size_t)(kt*64 + r)*QKVN + INNER + c4];
            *(float4*)&Ks[r*KS_STRIDE + c4] = *(const float4*)&krow[0];
            *(float4*)&Vs[r*64 + c4]        = *(const float4*)&krow[INNER];
        }
        __syncthreads();

        // S = (Q * scale) @ K^T : each thread 4 rows x 4 keys
        float s[4][4] = {};
#pragma unroll 4
        for (int d4 = 0; d4 < 16; d4++) {
            float4 a[4], bb[4];
#pragma unroll
            for (int i = 0; i < 4; i++) a[i]  = *(float4*)&Qs[(ty*4+i)*64 + d4*4];
#pragma unroll
            for (int j = 0; j < 4; j++) bb[j] = *(float4*)&Ks[(tx*4+j)*KS_STRIDE + d4*4];
#pragma unroll
            for (int i = 0; i < 4; i++)
#pragma unroll
                for (int j = 0; j < 4; j++)
                    s[i][j] += a[i].x*bb[j].x + a[i].y*bb[j].y
                             + a[i].z*bb[j].z + a[i].w*bb[j].w;
        }

        // Online softmax: reduce across the 16 tx lanes (stay inside 16-lane half)
        float p[4][4];
#pragma unroll
        for (int i = 0; i < 4; i++) {
            float tm = fmaxf(fmaxf(s[i][0], s[i][1]), fmaxf(s[i][2], s[i][3]));
#pragma unroll
            for (int off = 8; off; off >>= 1)
                tm = fmaxf(tm, __shfl_xor_sync(0xffffffffu, tm, off));
            float mnew = fmaxf(mi[i], tm);
            float scl = __expf(mi[i] - mnew);   // exp(-inf)=0 on first tile
            mi[i] = mnew;
            float ps = 0.f;
#pragma unroll
            for (int j = 0; j < 4; j++) { p[i][j] = __expf(s[i][j] - mnew); ps += p[i][j]; }
#pragma unroll
            for (int off = 8; off; off >>= 1)
                ps += __shfl_xor_sync(0xffffffffu, ps, off);
            li[i] = li[i]*scl + ps;
#pragma unroll
            for (int j = 0; j < 4; j++) o[i][j] *= scl;
        }

        __syncthreads();   // everyone done reading Ks
#pragma unroll
        for (int i = 0; i < 4; i++)
            *(float4*)&Ks[(ty*4+i)*KS_STRIDE + tx*4] =
                make_float4(p[i][0], p[i][1], p[i][2], p[i][3]);
        __syncthreads();

        // O += P @ V : thread owns 4 rows x 4 d-cols
#pragma unroll 8
        for (int key = 0; key < 64; key++) {
            float4 v = *(float4*)&Vs[key*64 + tx*4];
#pragma unroll
            for (int i = 0; i < 4; i++) {
                float pp = Ks[(ty*4+i)*KS_STRIDE + key];
                o[i][0] = fmaf(pp, v.x, o[i][0]);
                o[i][1] = fmaf(pp, v.y, o[i][1]);
                o[i][2] = fmaf(pp, v.z, o[i][2]);
                o[i][3] = fmaf(pp, v.w, o[i][3]);
            }
        }
    }

#pragma unroll
    for (int i = 0; i < 4; i++) {
        float inv = 1.f / li[i];
        int row = qt*64 + ty*4 + i;
        float4 r = make_float4(o[i][0]*inv, o[i][1]*inv, o[i][2]*inv, o[i][3]*inv);
        *(float4*)&out[((size_t)(b*NN + row))*INNER + h*DHEAD + tx*4] = r;
    }
}

// ---------------------------------------------------------------------------
extern "C" void kernel_launch(void* const* d_in, const int* in_sizes, int n_in,
                              void* d_out, int out_size) {
    const float* x      = (const float*)d_in[0];
    const float* shift  = (const float*)d_in[1];
    const float* scale  = (const float*)d_in[2];
    const float* norm_w = (const float*)d_in[3];
    const float* norm_b = (const float*)d_in[4];
    const float* w_qkv  = (const float*)d_in[5];
    const float* w_out  = (const float*)d_in[6];
    const float* b_out  = (const float*)d_in[7];
    float* out = (float*)d_out;

    float *hp, *qkvp, *attnp;
    cudaGetSymbolAddress((void**)&hp,    g_h);
    cudaGetSymbolAddress((void**)&qkvp,  g_qkv);
    cudaGetSymbolAddress((void**)&attnp, g_attn);

    const int attn_smem = ATTN_SMEM_FLOATS * (int)sizeof(float);   // 50176 B
    cudaFuncSetAttribute(attn_kernel,
                         cudaFuncAttributeMaxDynamicSharedMemorySize, attn_smem);

    ln_mod_kernel<<<TOK/8, 256>>>(x, shift, scale, norm_w, norm_b);
    sgemm_kernel<<<dim3(QKVN/64, TOK/64), 256>>>(hp, w_qkv, nullptr, qkvp,
                                                 TOK, QKVN, DIM);
    attn_kernel<<<dim3(16, BB*HEADS), 256, attn_smem>>>(qkvp, attnp);
    sgemm_kernel<<<dim3(DIM/64, TOK/64), 256>>>(attnp, w_out, b_out, out,
                                                TOK, DIM, INNER);
}

// round 2
// speedup vs baseline: 3.4734x; 3.4734x over previous
#include <cuda_runtime.h>
#include <math.h>
#include <stdint.h>

#define BB 8
#define NN 1024
#define DIM 192
#define HEADS 16
#define DHEAD 64
#define INNER 1024
#define TOK (BB*NN)       // 8192
#define QKVN (3*INNER)    // 3072

// Scratch (allocation-free rule: __device__ globals)
__device__ float g_h[TOK*DIM];
__device__ float g_qkv[(size_t)TOK*QKVN];
__device__ float g_attn[(size_t)TOK*INNER];

__device__ __forceinline__ uint32_t f2tf(float x){
    uint32_t u; asm("cvt.rna.tf32.f32 %0, %1;" : "=r"(u) : "f"(x)); return u;
}

// D += A@B, m16n8k8 tf32. c layout: c0=[g][2t], c1=[g][2t+1], c2=[g+8][2t], c3=[g+8][2t+1]
__device__ __forceinline__ void mma_tf32(float* c, uint32_t a0, uint32_t a1, uint32_t a2, uint32_t a3,
                                         uint32_t b0, uint32_t b1){
    asm volatile("mma.sync.aligned.m16n8k8.row.col.f32.tf32.tf32.f32 "
        "{%0,%1,%2,%3}, {%4,%5,%6,%7}, {%8,%9}, {%0,%1,%2,%3};"
        : "+f"(c[0]), "+f"(c[1]), "+f"(c[2]), "+f"(c[3])
        : "r"(a0), "r"(a1), "r"(a2), "r"(a3), "r"(b0), "r"(b1));
}

// ---------------------------------------------------------------------------
// LayerNorm + adaLN modulation: one warp per token
// ---------------------------------------------------------------------------
__global__ __launch_bounds__(256)
void ln_mod_kernel(const float* __restrict__ x,
                   const float* __restrict__ shift,
                   const float* __restrict__ scale,
                   const float* __restrict__ w,
                   const float* __restrict__ bpar) {
    int warp = threadIdx.x >> 5;
    int lane = threadIdx.x & 31;
    int t = blockIdx.x * 8 + warp;
    const float* xr = x + (size_t)t * DIM;
    float v[6];
    float s = 0.f;
#pragma unroll
    for (int q = 0; q < 6; q++) { v[q] = xr[lane + q*32]; s += v[q]; }
#pragma unroll
    for (int o = 16; o; o >>= 1) s += __shfl_xor_sync(0xffffffffu, s, o);
    float mu = s * (1.f/DIM);
    float vs = 0.f;
#pragma unroll
    for (int q = 0; q < 6; q++) { float d = v[q]-mu; vs += d*d; }
#pragma unroll
    for (int o = 16; o; o >>= 1) vs += __shfl_xor_sync(0xffffffffu, vs, o);
    float rstd = rsqrtf(vs*(1.f/DIM) + 1e-5f);
    int bi = t >> 10;
#pragma unroll
    for (int q = 0; q < 6; q++) {
        int d = lane + q*32;
        float hn = (v[q]-mu)*rstd*w[d] + bpar[d];
        hn = hn * (1.f + scale[bi*DIM + d]) + shift[bi*DIM + d];
        g_h[(size_t)t*DIM + d] = hn;
    }
}

// ---------------------------------------------------------------------------
// tf32 tensor-core GEMM: C[M,Nn] = A[M,K]@B[K,N] (+bias). BM=128 BN=64 BK=32.
// 8 warps, warp tile 32x32 (2 mfrag x 4 nfrag), m16n8k8.
// ---------------------------------------------------------------------------
#define GA_STR 36
#define GB_STR 68

__global__ __launch_bounds__(256)
void gemm_tc(const float* __restrict__ A, const float* __restrict__ Bm,
             const float* __restrict__ bias, float* __restrict__ C,
             int M, int Nn, int K){
    __shared__ uint32_t As[128*GA_STR];
    __shared__ uint32_t Bs[32*GB_STR];
    int m0 = blockIdx.y*128, n0 = blockIdx.x*64;
    int tid = threadIdx.x;
    int w = tid>>5, lane = tid&31;
    int g = lane>>2, t = lane&3;
    int wm = w>>1, wn = w&1;
    float acc[2][4][4] = {};

    for (int kt = 0; kt < K; kt += 32){
#pragma unroll
        for (int i = 0; i < 4; i++){
            int fid = tid + i*256;
            int r = fid>>3, cq = fid&7;
            float4 v = *(const float4*)&A[(size_t)(m0+r)*K + kt + cq*4];
            uint4 u = make_uint4(f2tf(v.x), f2tf(v.y), f2tf(v.z), f2tf(v.w));
            *(uint4*)&As[r*GA_STR + cq*4] = u;
        }
#pragma unroll
        for (int i = 0; i < 2; i++){
            int fid = tid + i*256;
            int r = fid>>4, cq = fid&15;
            float4 v = *(const float4*)&Bm[(size_t)(kt+r)*Nn + n0 + cq*4];
            uint4 u = make_uint4(f2tf(v.x), f2tf(v.y), f2tf(v.z), f2tf(v.w));
            *(uint4*)&Bs[r*GB_STR + cq*4] = u;
        }
        __syncthreads();
#pragma unroll
        for (int ks = 0; ks < 4; ks++){
            int k0 = ks*8;
            uint32_t a[2][4];
#pragma unroll
            for (int mf = 0; mf < 2; mf++){
                int row = wm*32 + mf*16 + g;
                a[mf][0] = As[row*GA_STR + k0 + t];
                a[mf][1] = As[(row+8)*GA_STR + k0 + t];
                a[mf][2] = As[row*GA_STR + k0 + 4 + t];
                a[mf][3] = As[(row+8)*GA_STR + k0 + 4 + t];
            }
#pragma unroll
            for (int nf = 0; nf < 4; nf++){
                int col = wn*32 + nf*8 + g;
                uint32_t b0 = Bs[(k0+t)*GB_STR + col];
                uint32_t b1 = Bs[(k0+4+t)*GB_STR + col];
                mma_tf32(acc[0][nf], a[0][0],a[0][1],a[0][2],a[0][3], b0,b1);
                mma_tf32(acc[1][nf], a[1][0],a[1][1],a[1][2],a[1][3], b0,b1);
            }
        }
        __syncthreads();
    }
#pragma unroll
    for (int mf = 0; mf < 2; mf++){
#pragma unroll
        for (int nf = 0; nf < 4; nf++){
            int row = m0 + wm*32 + mf*16 + g;
            int col = n0 + wn*32 + nf*8 + t*2;
            float bx = 0.f, by = 0.f;
            if (bias){ bx = bias[col]; by = bias[col+1]; }
            *(float2*)&C[(size_t)row*Nn + col] =
                make_float2(acc[mf][nf][0]+bx, acc[mf][nf][1]+by);
            *(float2*)&C[(size_t)(row+8)*Nn + col] =
                make_float2(acc[mf][nf][2]+bx, acc[mf][nf][3]+by);
        }
    }
}

// ---------------------------------------------------------------------------
// Flash attention, tf32 tensor cores. 128 threads; each warp owns 16 q-rows.
// Per block: q-tile 64 x (b,h). K/V streamed in 64-key tiles.
// S and P per warp stay warp-private (P via smem round-trip + __syncwarp).
// ---------------------------------------------------------------------------
#define AT_STR 68
#define ATTN_SMEM_BYTES (4*64*AT_STR*4)   // Qs,Ks,Vs,Ps  = 69632

__global__ __launch_bounds__(128)
void attn_tc(const float* __restrict__ qkv, float* __restrict__ out){
    extern __shared__ uint32_t sm[];
    uint32_t* Qs = sm;
    uint32_t* Ks = Qs + 64*AT_STR;
    uint32_t* Vs = Ks + 64*AT_STR;
    uint32_t* Ps = Vs + 64*AT_STR;

    int qt = blockIdx.x, bh = blockIdx.y;
    int b = bh>>4, h = bh&15;
    int tid = threadIdx.x, w = tid>>5, lane = tid&31;
    int g = lane>>2, t = lane&3;
    const float* base = qkv + (size_t)b*NN*QKVN + h*DHEAD;

    // Q tile (fold softmax scale 0.125)
#pragma unroll
    for (int i = 0; i < 8; i++){
        int fid = tid + i*128;
        int r = fid>>4, cq = fid&15;
        float4 v = *(const float4*)&base[(size_t)(qt*64+r)*QKVN + cq*4];
        *(uint4*)&Qs[r*AT_STR + cq*4] = make_uint4(
            f2tf(v.x*0.125f), f2tf(v.y*0.125f), f2tf(v.z*0.125f), f2tf(v.w*0.125f));
    }

    float o[8][4] = {};
    float mi0 = -INFINITY, mi1 = -INFINITY, li0 = 0.f, li1 = 0.f;

    for (int kt = 0; kt < 16; kt++){
        __syncthreads();   // previous tile's Ks/Vs readers done
#pragma unroll
        for (int i = 0; i < 8; i++){
            int fid = tid + i*128;
            int r = fid>>4, cq = fid&15;
            const float* kr = &base[(size_t)(kt*64+r)*QKVN + INNER + cq*4];
            float4 kv = *(const float4*)kr;
            float4 vv = *(const float4*)(kr + INNER);
            *(uint4*)&Ks[r*AT_STR + cq*4] = make_uint4(f2tf(kv.x),f2tf(kv.y),f2tf(kv.z),f2tf(kv.w));
            *(uint4*)&Vs[r*AT_STR + cq*4] = make_uint4(f2tf(vv.x),f2tf(vv.y),f2tf(vv.z),f2tf(vv.w));
        }
        __syncthreads();

        // S = Q @ K^T   (warp rows w*16 .. w*16+15, all 64 keys)
        float s[8][4] = {};
        int row = w*16 + g;
#pragma unroll
        for (int ks = 0; ks < 8; ks++){
            int k0 = ks*8;
            uint32_t a0 = Qs[row*AT_STR + k0 + t];
            uint32_t a1 = Qs[(row+8)*AT_STR + k0 + t];
            uint32_t a2 = Qs[row*AT_STR + k0 + 4 + t];
            uint32_t a3 = Qs[(row+8)*AT_STR + k0 + 4 + t];
#pragma unroll
            for (int nf = 0; nf < 8; nf++){
                int key = nf*8 + g;
                uint32_t b0 = Ks[key*AT_STR + k0 + t];
                uint32_t b1 = Ks[key*AT_STR + k0 + 4 + t];
                mma_tf32(s[nf], a0, a1, a2, a3, b0, b1);
            }
        }

        // Online softmax. Thread holds rows (row) via c0,c1 and (row+8) via c2,c3;
        // 64 cols spread over the 4 lanes of the quad -> reduce with xor 1,2.
        float mx0 = -INFINITY, mx1 = -INFINITY;
#pragma unroll
        for (int nf = 0; nf < 8; nf++){
            mx0 = fmaxf(mx0, fmaxf(s[nf][0], s[nf][1]));
            mx1 = fmaxf(mx1, fmaxf(s[nf][2], s[nf][3]));
        }
        mx0 = fmaxf(mx0, __shfl_xor_sync(0xffffffffu, mx0, 1));
        mx0 = fmaxf(mx0, __shfl_xor_sync(0xffffffffu, mx0, 2));
        mx1 = fmaxf(mx1, __shfl_xor_sync(0xffffffffu, mx1, 1));
        mx1 = fmaxf(mx1, __shfl_xor_sync(0xffffffffu, mx1, 2));
        float mn0 = fmaxf(mi0, mx0), mn1 = fmaxf(mi1, mx1);
        float sc0 = __expf(mi0 - mn0), sc1 = __expf(mi1 - mn1);
        mi0 = mn0; mi1 = mn1;

        __syncwarp();      // prior PV reads of Ps done before overwrite
        float sum0 = 0.f, sum1 = 0.f;
#pragma unroll
        for (int nf = 0; nf < 8; nf++){
            float p0 = __expf(s[nf][0] - mn0), p1 = __expf(s[nf][1] - mn0);
            float p2 = __expf(s[nf][2] - mn1), p3 = __expf(s[nf][3] - mn1);
            sum0 += p0 + p1; sum1 += p2 + p3;
            int col = nf*8 + t*2;
            *(uint2*)&Ps[row*AT_STR + col]     = make_uint2(f2tf(p0), f2tf(p1));
            *(uint2*)&Ps[(row+8)*AT_STR + col] = make_uint2(f2tf(p2), f2tf(p3));
        }
        sum0 += __shfl_xor_sync(0xffffffffu, sum0, 1);
        sum0 += __shfl_xor_sync(0xffffffffu, sum0, 2);
        sum1 += __shfl_xor_sync(0xffffffffu, sum1, 1);
        sum1 += __shfl_xor_sync(0xffffffffu, sum1, 2);
        li0 = li0*sc0 + sum0;
        li1 = li1*sc1 + sum1;
#pragma unroll
        for (int nf = 0; nf < 8; nf++){
            o[nf][0] *= sc0; o[nf][1] *= sc0;
            o[nf][2] *= sc1; o[nf][3] *= sc1;
        }
        __syncwarp();      // Ps visible to the whole warp

        // O += P @ V
#pragma unroll
        for (int ks = 0; ks < 8; ks++){
            int k0 = ks*8;
            uint32_t a0 = Ps[row*AT_STR + k0 + t];
            uint32_t a1 = Ps[(row+8)*AT_STR + k0 + t];
            uint32_t a2 = Ps[row*AT_STR + k0 + 4 + t];
            uint32_t a3 = Ps[(row+8)*AT_STR + k0 + 4 + t];
#pragma unroll
            for (int nf = 0; nf < 8; nf++){
                int d0 = nf*8 + g;
                uint32_t b0 = Vs[(k0+t)*AT_STR + d0];
                uint32_t b1 = Vs[(k0+4+t)*AT_STR + d0];
                mma_tf32(o[nf], a0, a1, a2, a3, b0, b1);
            }
        }
    }

    float inv0 = 1.f/li0, inv1 = 1.f/li1;
    int row = qt*64 + w*16 + g;
#pragma unroll
    for (int nf = 0; nf < 8; nf++){
        int col = h*DHEAD + nf*8 + t*2;
        *(float2*)&out[((size_t)(b*NN+row))*INNER + col]   =
            make_float2(o[nf][0]*inv0, o[nf][1]*inv0);
        *(float2*)&out[((size_t)(b*NN+row+8))*INNER + col] =
            make_float2(o[nf][2]*inv1, o[nf][3]*inv1);
    }
}

// ---------------------------------------------------------------------------
extern "C" void kernel_launch(void* const* d_in, const int* in_sizes, int n_in,
                              void* d_out, int out_size) {
    const float* x      = (const float*)d_in[0];
    const float* shift  = (const float*)d_in[1];
    const float* scale  = (const float*)d_in[2];
    const float* norm_w = (const float*)d_in[3];
    const float* norm_b = (const float*)d_in[4];
    const float* w_qkv  = (const float*)d_in[5];
    const float* w_out  = (const float*)d_in[6];
    const float* b_out  = (const float*)d_in[7];
    float* out = (float*)d_out;

    float *hp, *qkvp, *attnp;
    cudaGetSymbolAddress((void**)&hp,    g_h);
    cudaGetSymbolAddress((void**)&qkvp,  g_qkv);
    cudaGetSymbolAddress((void**)&attnp, g_attn);

    cudaFuncSetAttribute(attn_tc,
                         cudaFuncAttributeMaxDynamicSharedMemorySize, ATTN_SMEM_BYTES);

    ln_mod_kernel<<<TOK/8, 256>>>(x, shift, scale, norm_w, norm_b);
    gemm_tc<<<dim3(QKVN/64, TOK/128), 256>>>(hp, w_qkv, nullptr, qkvp,
                                             TOK, QKVN, DIM);
    attn_tc<<<dim3(16, BB*HEADS), 128, ATTN_SMEM_BYTES>>>(qkvp, attnp);
    gemm_tc<<<dim3(DIM/64, TOK/128), 256>>>(attnp, w_out, b_out, out,
                                            TOK, DIM, INNER);
}

// round 3
// speedup vs baseline: 4.3569x; 1.2544x over previous
#include <cuda_runtime.h>
#include <math.h>
#include <stdint.h>

#define BB 8
#define NN 1024
#define DIM 192
#define HEADS 16
#define DHEAD 64
#define INNER 1024
#define TOK (BB*NN)       // 8192
#define QKVN (3*INNER)    // 3072

// Scratch (allocation-free rule: __device__ globals)
__device__ float g_h[TOK*DIM];
__device__ float g_qkv[(size_t)TOK*QKVN];
__device__ float g_attn[(size_t)TOK*INNER];

__device__ __forceinline__ uint32_t f2tf(float x){
    uint32_t u; asm("cvt.rna.tf32.f32 %0, %1;" : "=r"(u) : "f"(x)); return u;
}

// D += A@B, m16n8k8 tf32. c0=[g][2t], c1=[g][2t+1], c2=[g+8][2t], c3=[g+8][2t+1]
__device__ __forceinline__ void mma_tf32(float* c, uint32_t a0, uint32_t a1, uint32_t a2, uint32_t a3,
                                         uint32_t b0, uint32_t b1){
    asm volatile("mma.sync.aligned.m16n8k8.row.col.f32.tf32.tf32.f32 "
        "{%0,%1,%2,%3}, {%4,%5,%6,%7}, {%8,%9}, {%0,%1,%2,%3};"
        : "+f"(c[0]), "+f"(c[1]), "+f"(c[2]), "+f"(c[3])
        : "r"(a0), "r"(a1), "r"(a2), "r"(a3), "r"(b0), "r"(b1));
}

// ldmatrix.x4 on 32-bit data: each 8x8-b16 matrix == 8 rows x 4 fp32.
// Thread lane gets reg j = matrix j, row lane/4, float-col lane%4.
__device__ __forceinline__ void ldsm4(uint32_t* r, uint32_t saddr){
    asm volatile("ldmatrix.sync.aligned.m8n8.x4.shared.b16 {%0,%1,%2,%3}, [%4];"
        : "=r"(r[0]), "=r"(r[1]), "=r"(r[2]), "=r"(r[3]) : "r"(saddr));
}

// ---------------------------------------------------------------------------
// LayerNorm + adaLN modulation: one warp per token
// ---------------------------------------------------------------------------
__global__ __launch_bounds__(256)
void ln_mod_kernel(const float* __restrict__ x,
                   const float* __restrict__ shift,
                   const float* __restrict__ scale,
                   const float* __restrict__ w,
                   const float* __restrict__ bpar) {
    int warp = threadIdx.x >> 5;
    int lane = threadIdx.x & 31;
    int t = blockIdx.x * 8 + warp;
    const float* xr = x + (size_t)t * DIM;
    float v[6];
    float s = 0.f;
#pragma unroll
    for (int q = 0; q < 6; q++) { v[q] = xr[lane + q*32]; s += v[q]; }
#pragma unroll
    for (int o = 16; o; o >>= 1) s += __shfl_xor_sync(0xffffffffu, s, o);
    float mu = s * (1.f/DIM);
    float vs = 0.f;
#pragma unroll
    for (int q = 0; q < 6; q++) { float d = v[q]-mu; vs += d*d; }
#pragma unroll
    for (int o = 16; o; o >>= 1) vs += __shfl_xor_sync(0xffffffffu, vs, o);
    float rstd = rsqrtf(vs*(1.f/DIM) + 1e-5f);
    int bi = t >> 10;
#pragma unroll
    for (int q = 0; q < 6; q++) {
        int d = lane + q*32;
        float hn = (v[q]-mu)*rstd*w[d] + bpar[d];
        hn = hn * (1.f + scale[bi*DIM + d]) + shift[bi*DIM + d];
        g_h[(size_t)t*DIM + d] = hn;
    }
}

// ---------------------------------------------------------------------------
// tf32 TC GEMM, templated BM (128 or 64). BN=64, BK=32, 256 thr.
// LDSM A-frags, scalar B-frags, register-prefetch global pipeline.
// ---------------------------------------------------------------------------
#define GA_STR 36
#define GB_STR 72

template<int BM>
__global__ __launch_bounds__(256)
void gemm_tc(const float* __restrict__ A, const float* __restrict__ Bm,
             const float* __restrict__ bias, float* __restrict__ C,
             int M, int Nn, int K){
    constexpr int WROWS = BM/32;        // warps along m
    constexpr int WCOLS = 8/WROWS;      // warps along n
    constexpr int NFR   = (64/WCOLS)/8; // 8-col frags per warp
    constexpr int AIT   = BM/32;        // A-load float4 iters per thread
    __shared__ uint32_t As[BM*GA_STR];
    __shared__ uint32_t Bs[32*GB_STR];
    int m0 = blockIdx.y*BM, n0 = blockIdx.x*64;
    int tid = threadIdx.x;
    int w = tid>>5, lane = tid&31;
    int g = lane>>2, t = lane&3;
    int wm = w / WCOLS, wn = w % WCOLS;
    uint32_t as_sh = (uint32_t)__cvta_generic_to_shared(As);
    uint32_t bs_sh = (uint32_t)__cvta_generic_to_shared(Bs);
    // LDSM lane addressing for A frags
    int a_sub = ((lane>>3)&1)*8 + (lane&7);
    int a_kh  = (lane>>4)*4;

    float acc[2][NFR][4] = {};
    float4 ra[AIT], rb[2];

    // prefetch tile 0
#pragma unroll
    for (int i = 0; i < AIT; i++){
        int fid = tid + i*256; int r = fid>>3, cq = fid&7;
        ra[i] = *(const float4*)&A[(size_t)(m0+r)*K + cq*4];
    }
#pragma unroll
    for (int i = 0; i < 2; i++){
        int fid = tid + i*256; int r = fid>>4, cq = fid&15;
        rb[i] = *(const float4*)&Bm[(size_t)r*Nn + n0 + cq*4];
    }

    for (int kt = 0; kt < K; kt += 32){
        // store current tile (convert to tf32)
#pragma unroll
        for (int i = 0; i < AIT; i++){
            int fid = tid + i*256; int r = fid>>3, cq = fid&7;
            *(uint4*)&As[r*GA_STR + cq*4] =
                make_uint4(f2tf(ra[i].x), f2tf(ra[i].y), f2tf(ra[i].z), f2tf(ra[i].w));
        }
#pragma unroll
        for (int i = 0; i < 2; i++){
            int fid = tid + i*256; int r = fid>>4, cq = fid&15;
            *(uint4*)&Bs[r*GB_STR + cq*4] =
                make_uint4(f2tf(rb[i].x), f2tf(rb[i].y), f2tf(rb[i].z), f2tf(rb[i].w));
        }
        __syncthreads();
        // prefetch next tile into registers (overlaps with MMAs below)
        if (kt + 32 < K){
#pragma unroll
            for (int i = 0; i < AIT; i++){
                int fid = tid + i*256; int r = fid>>3, cq = fid&7;
                ra[i] = *(const float4*)&A[(size_t)(m0+r)*K + kt + 32 + cq*4];
            }
#pragma unroll
            for (int i = 0; i < 2; i++){
                int fid = tid + i*256; int r = fid>>4, cq = fid&15;
                rb[i] = *(const float4*)&Bm[(size_t)(kt+32+r)*Nn + n0 + cq*4];
            }
        }
#pragma unroll
        for (int ks = 0; ks < 4; ks++){
            int k0 = ks*8;
            uint32_t af[2][4];
#pragma unroll
            for (int mf = 0; mf < 2; mf++){
                int row = wm*32 + mf*16 + a_sub;
                ldsm4(af[mf], as_sh + (uint32_t)(row*GA_STR + k0 + a_kh)*4);
            }
#pragma unroll
            for (int nf = 0; nf < NFR; nf++){
                int col = wn*(64/WCOLS) + nf*8 + g;
                uint32_t b0 = Bs[(k0+t)*GB_STR + col];
                uint32_t b1 = Bs[(k0+4+t)*GB_STR + col];
                mma_tf32(acc[0][nf], af[0][0],af[0][1],af[0][2],af[0][3], b0,b1);
                mma_tf32(acc[1][nf], af[1][0],af[1][1],af[1][2],af[1][3], b0,b1);
            }
        }
        __syncthreads();
    }
#pragma unroll
    for (int mf = 0; mf < 2; mf++){
#pragma unroll
        for (int nf = 0; nf < NFR; nf++){
            int row = m0 + wm*32 + mf*16 + g;
            int col = n0 + wn*(64/WCOLS) + nf*8 + t*2;
            float bx = 0.f, by = 0.f;
            if (bias){ bx = bias[col]; by = bias[col+1]; }
            *(float2*)&C[(size_t)row*Nn + col] =
                make_float2(acc[mf][nf][0]+bx, acc[mf][nf][1]+by);
            *(float2*)&C[(size_t)(row+8)*Nn + col] =
                make_float2(acc[mf][nf][2]+bx, acc[mf][nf][3]+by);
        }
    }
}

// ---------------------------------------------------------------------------
// Flash attention, tf32 TC. 128 thr; warp owns 16 q-rows.
// Q frags in registers (LDSM once); Ps reuses Q smem; K frags + P frags via LDSM.
// ---------------------------------------------------------------------------
#define AT_STR 68
#define V_STR  72
#define ATTN_SMEM_BYTES ((2*64*AT_STR + 64*V_STR)*4)   // 53248

__global__ __launch_bounds__(128, 3)
void attn_tc(const float* __restrict__ qkv, float* __restrict__ out){
    extern __shared__ uint32_t sm[];
    uint32_t* Ps = sm;                    // Q staging, then P
    uint32_t* Ks = sm + 64*AT_STR;
    uint32_t* Vs = sm + 2*64*AT_STR;      // stride V_STR

    int qt = blockIdx.x, bh = blockIdx.y;
    int b = bh>>4, h = bh&15;
    int tid = threadIdx.x, w = tid>>5, lane = tid&31;
    int g = lane>>2, t = lane&3;
    const float* base = qkv + (size_t)b*NN*QKVN + h*DHEAD;

    uint32_t ps_sh = (uint32_t)__cvta_generic_to_shared(Ps);
    uint32_t ks_sh = (uint32_t)__cvta_generic_to_shared(Ks);
    // A-frag lane addressing (Q and P): rows w*16..w*16+15
    int a_row = w*16 + ((lane>>3)&1)*8 + (lane&7);
    int a_kh  = (lane>>4)*4;
    uint32_t a_base = ps_sh + (uint32_t)(a_row*AT_STR + a_kh)*4;
    // B-frag lane addressing (K): two 8-key blocks per LDSM
    int kb_row = ((lane>>4)<<3) + (lane&7);
    int kb_kh  = ((lane>>3)&1)*4;
    uint32_t kb_base = ks_sh + (uint32_t)(kb_row*AT_STR + kb_kh)*4;

    // Load Q tile into Ps region (scale folded), then pull frags to registers
#pragma unroll
    for (int i = 0; i < 8; i++){
        int fid = tid + i*128;
        int r = fid>>4, cq = fid&15;
        float4 v = *(const float4*)&base[(size_t)(qt*64+r)*QKVN + cq*4];
        *(uint4*)&Ps[r*AT_STR + cq*4] = make_uint4(
            f2tf(v.x*0.125f), f2tf(v.y*0.125f), f2tf(v.z*0.125f), f2tf(v.w*0.125f));
    }
    __syncthreads();
    uint32_t qf[8][4];
#pragma unroll
    for (int ks = 0; ks < 8; ks++)
        ldsm4(qf[ks], a_base + ks*32);

    float o[8][4] = {};
    float mi0 = -INFINITY, mi1 = -INFINITY, li0 = 0.f, li1 = 0.f;

    for (int kt = 0; kt < 16; kt++){
        __syncthreads();   // previous tile's Ks/Vs readers done
#pragma unroll
        for (int i = 0; i < 8; i++){
            int fid = tid + i*128;
            int r = fid>>4, cq = fid&15;
            const float* kr = &base[(size_t)(kt*64+r)*QKVN + INNER + cq*4];
            float4 kv = *(const float4*)kr;
            float4 vv = *(const float4*)(kr + INNER);
            *(uint4*)&Ks[r*AT_STR + cq*4] = make_uint4(f2tf(kv.x),f2tf(kv.y),f2tf(kv.z),f2tf(kv.w));
            *(uint4*)&Vs[r*V_STR  + cq*4] = make_uint4(f2tf(vv.x),f2tf(vv.y),f2tf(vv.z),f2tf(vv.w));
        }
        __syncthreads();

        // S = Q @ K^T
        float s[8][4] = {};
#pragma unroll
        for (int ks = 0; ks < 8; ks++){
            uint32_t* a = qf[ks];
#pragma unroll
            for (int nfp = 0; nfp < 4; nfp++){
                uint32_t kb[4];
                ldsm4(kb, kb_base + (uint32_t)(nfp*16*AT_STR)*4 + ks*32);
                mma_tf32(s[2*nfp],   a[0],a[1],a[2],a[3], kb[0], kb[1]);
                mma_tf32(s[2*nfp+1], a[0],a[1],a[2],a[3], kb[2], kb[3]);
            }
        }

        // Online softmax: reduce across the 4 quad lanes (xor 1,2)
        float mx0 = -INFINITY, mx1 = -INFINITY;
#pragma unroll
        for (int nf = 0; nf < 8; nf++){
            mx0 = fmaxf(mx0, fmaxf(s[nf][0], s[nf][1]));
            mx1 = fmaxf(mx1, fmaxf(s[nf][2], s[nf][3]));
        }
        mx0 = fmaxf(mx0, __shfl_xor_sync(0xffffffffu, mx0, 1));
        mx0 = fmaxf(mx0, __shfl_xor_sync(0xffffffffu, mx0, 2));
        mx1 = fmaxf(mx1, __shfl_xor_sync(0xffffffffu, mx1, 1));
        mx1 = fmaxf(mx1, __shfl_xor_sync(0xffffffffu, mx1, 2));
        float mn0 = fmaxf(mi0, mx0), mn1 = fmaxf(mi1, mx1);
        float sc0 = __expf(mi0 - mn0), sc1 = __expf(mi1 - mn1);
        mi0 = mn0; mi1 = mn1;

        __syncwarp();      // prior PV LDSM reads of Ps done (warp-private rows)
        int prow = w*16 + g;
        float sum0 = 0.f, sum1 = 0.f;
#pragma unroll
        for (int nf = 0; nf < 8; nf++){
            float p0 = __expf(s[nf][0] - mn0), p1 = __expf(s[nf][1] - mn0);
            float p2 = __expf(s[nf][2] - mn1), p3 = __expf(s[nf][3] - mn1);
            sum0 += p0 + p1; sum1 += p2 + p3;
            int col = nf*8 + t*2;
            *(uint2*)&Ps[prow*AT_STR + col]     = make_uint2(f2tf(p0), f2tf(p1));
            *(uint2*)&Ps[(prow+8)*AT_STR + col] = make_uint2(f2tf(p2), f2tf(p3));
        }
        sum0 += __shfl_xor_sync(0xffffffffu, sum0, 1);
        sum0 += __shfl_xor_sync(0xffffffffu, sum0, 2);
        sum1 += __shfl_xor_sync(0xffffffffu, sum1, 1);
        sum1 += __shfl_xor_sync(0xffffffffu, sum1, 2);
        li0 = li0*sc0 + sum0;
        li1 = li1*sc1 + sum1;
#pragma unroll
        for (int nf = 0; nf < 8; nf++){
            o[nf][0] *= sc0; o[nf][1] *= sc0;
            o[nf][2] *= sc1; o[nf][3] *= sc1;
        }
        __syncwarp();      // Ps visible warp-wide

        // O += P @ V
#pragma unroll
        for (int ks = 0; ks < 8; ks++){
            int k0 = ks*8;
            uint32_t pa[4];
            ldsm4(pa, a_base + ks*32);
#pragma unroll
            for (int nf = 0; nf < 8; nf++){
                int d0 = nf*8 + g;
                uint32_t b0 = Vs[(k0+t)*V_STR + d0];
                uint32_t b1 = Vs[(k0+4+t)*V_STR + d0];
                mma_tf32(o[nf], pa[0],pa[1],pa[2],pa[3], b0, b1);
            }
        }
    }

    float inv0 = 1.f/li0, inv1 = 1.f/li1;
    int row = qt*64 + w*16 + g;
#pragma unroll
    for (int nf = 0; nf < 8; nf++){
        int col = h*DHEAD + nf*8 + t*2;
        *(float2*)&out[((size_t)(b*NN+row))*INNER + col]   =
            make_float2(o[nf][0]*inv0, o[nf][1]*inv0);
        *(float2*)&out[((size_t)(b*NN+row+8))*INNER + col] =
            make_float2(o[nf][2]*inv1, o[nf][3]*inv1);
    }
}

// ---------------------------------------------------------------------------
extern "C" void kernel_launch(void* const* d_in, const int* in_sizes, int n_in,
                              void* d_out, int out_size) {
    const float* x      = (const float*)d_in[0];
    const float* shift  = (const float*)d_in[1];
    const float* scale  = (const float*)d_in[2];
    const float* norm_w = (const float*)d_in[3];
    const float* norm_b = (const float*)d_in[4];
    const float* w_qkv  = (const float*)d_in[5];
    const float* w_out  = (const float*)d_in[6];
    const float* b_out  = (const float*)d_in[7];
    float* out = (float*)d_out;

    float *hp, *qkvp, *attnp;
    cudaGetSymbolAddress((void**)&hp,    g_h);
    cudaGetSymbolAddress((void**)&qkvp,  g_qkv);
    cudaGetSymbolAddress((void**)&attnp, g_attn);

    cudaFuncSetAttribute(attn_tc,
                         cudaFuncAttributeMaxDynamicSharedMemorySize, ATTN_SMEM_BYTES);

    ln_mod_kernel<<<TOK/8, 256>>>(x, shift, scale, norm_w, norm_b);
    gemm_tc<128><<<dim3(QKVN/64, TOK/128), 256>>>(hp, w_qkv, nullptr, qkvp,
                                                  TOK, QKVN, DIM);
    attn_tc<<<dim3(16, BB*HEADS), 128, ATTN_SMEM_BYTES>>>(qkvp, attnp);
    gemm_tc<64><<<dim3(DIM/64, TOK/64), 256>>>(attnp, w_out, b_out, out,
                                               TOK, DIM, INNER);
}

// round 5
// speedup vs baseline: 5.2143x; 1.1968x over previous
#include <cuda_runtime.h>
#include <math.h>
#include <stdint.h>

#define BB 8
#define NN 1024
#define DIM 192
#define HEADS 16
#define DHEAD 64
#define INNER 1024
#define TOK (BB*NN)       // 8192
#define QKVN (3*INNER)    // 3072

// Scratch (allocation-free rule: __device__ globals)
__device__ float g_h[TOK*DIM];
__device__ float g_qkv[(size_t)TOK*QKVN];
__device__ float g_attn[(size_t)TOK*INNER];
__device__ float g_wqkv[DIM*QKVN];
__device__ float g_wout[INNER*DIM];

__device__ __forceinline__ uint32_t f2tf(float x){
    uint32_t u; asm("cvt.rna.tf32.f32 %0, %1;" : "=r"(u) : "f"(x)); return u;
}

// D += A@B, m16n8k8 tf32. c0=[g][2t], c1=[g][2t+1], c2=[g+8][2t], c3=[g+8][2t+1]
__device__ __forceinline__ void mma_tf32(float* c, uint32_t a0, uint32_t a1, uint32_t a2, uint32_t a3,
                                         uint32_t b0, uint32_t b1){
    asm volatile("mma.sync.aligned.m16n8k8.row.col.f32.tf32.tf32.f32 "
        "{%0,%1,%2,%3}, {%4,%5,%6,%7}, {%8,%9}, {%0,%1,%2,%3};"
        : "+f"(c[0]), "+f"(c[1]), "+f"(c[2]), "+f"(c[3])
        : "r"(a0), "r"(a1), "r"(a2), "r"(a3), "r"(b0), "r"(b1));
}

__device__ __forceinline__ void ldsm4(uint32_t* r, uint32_t saddr){
    asm volatile("ldmatrix.sync.aligned.m8n8.x4.shared.b16 {%0,%1,%2,%3}, [%4];"
        : "=r"(r[0]), "=r"(r[1]), "=r"(r[2]), "=r"(r[3]) : "r"(saddr));
}

__device__ __forceinline__ void cpa16(uint32_t dst, const void* src){
    asm volatile("cp.async.cg.shared.global [%0], [%1], 16;" :: "r"(dst), "l"(src));
}
__device__ __forceinline__ void cp_commit(){ asm volatile("cp.async.commit_group;"); }
template<int N> __device__ __forceinline__ void cp_wait(){
    asm volatile("cp.async.wait_group %0;" :: "n"(N));
}

// ---------------------------------------------------------------------------
// Elementwise fp32 -> tf32-rounded fp32 bits (for weights)
// ---------------------------------------------------------------------------
__global__ __launch_bounds__(256)
void cvt_tf32_kernel(const float* __restrict__ src, float* __restrict__ dst, int n){
    for (int i = blockIdx.x*256 + threadIdx.x; i < n; i += gridDim.x*256)
        dst[i] = __uint_as_float(f2tf(src[i]));
}

// ---------------------------------------------------------------------------
// LayerNorm + adaLN modulation: one warp per token; output tf32-rounded
// ---------------------------------------------------------------------------
__global__ __launch_bounds__(256)
void ln_mod_kernel(const float* __restrict__ x,
                   const float* __restrict__ shift,
                   const float* __restrict__ scale,
                   const float* __restrict__ w,
                   const float* __restrict__ bpar) {
    int warp = threadIdx.x >> 5;
    int lane = threadIdx.x & 31;
    int t = blockIdx.x * 8 + warp;
    const float* xr = x + (size_t)t * DIM;
    float v[6];
    float s = 0.f;
#pragma unroll
    for (int q = 0; q < 6; q++) { v[q] = xr[lane + q*32]; s += v[q]; }
#pragma unroll
    for (int o = 16; o; o >>= 1) s += __shfl_xor_sync(0xffffffffu, s, o);
    float mu = s * (1.f/DIM);
    float vs = 0.f;
#pragma unroll
    for (int q = 0; q < 6; q++) { float d = v[q]-mu; vs += d*d; }
#pragma unroll
    for (int o = 16; o; o >>= 1) vs += __shfl_xor_sync(0xffffffffu, vs, o);
    float rstd = rsqrtf(vs*(1.f/DIM) + 1e-5f);
    int bi = t >> 10;
#pragma unroll
    for (int q = 0; q < 6; q++) {
        int d = lane + q*32;
        float hn = (v[q]-mu)*rstd*w[d] + bpar[d];
        hn = hn * (1.f + scale[bi*DIM + d]) + shift[bi*DIM + d];
        g_h[(size_t)t*DIM + d] = __uint_as_float(f2tf(hn));
    }
}

// ---------------------------------------------------------------------------
// tf32 TC GEMM. Inputs already tf32-rounded. cp.async double-buffered.
// BN=64, BK=32, 256 thr. bias==nullptr => output tf32-rounded (QKV path).
// ---------------------------------------------------------------------------
#define GA_STR 36
#define GB_STR 72

template<int BM>
__global__ __launch_bounds__(256)
void gemm_tc(const float* __restrict__ A, const float* __restrict__ Bm,
             const float* __restrict__ bias, float* __restrict__ C,
             int M, int Nn, int K){
    constexpr int WROWS = BM/32;
    constexpr int WCOLS = 8/WROWS;
    constexpr int NFR   = (64/WCOLS)/8;
    constexpr int AIT   = BM*8/256;      // 16B chunks per thread for A
    constexpr int ABUF  = BM*GA_STR;
    constexpr int BBUF  = 32*GB_STR;
    extern __shared__ uint32_t smg[];
    uint32_t* As = smg;                  // 2 buffers
    uint32_t* Bs = smg + 2*ABUF;         // 2 buffers
    int m0 = blockIdx.y*BM, n0 = blockIdx.x*64;
    int tid = threadIdx.x;
    int w = tid>>5, lane = tid&31;
    int g = lane>>2, t = lane&3;
    int wm = w / WCOLS, wn = w % WCOLS;
    uint32_t as_sh = (uint32_t)__cvta_generic_to_shared(As);
    uint32_t bs_sh = (uint32_t)__cvta_generic_to_shared(Bs);
    int a_sub = ((lane>>3)&1)*8 + (lane&7);
    int a_kh  = (lane>>4)*4;

    float acc[2][NFR][4] = {};

    auto issue = [&](int kt, int buf){
#pragma unroll
        for (int i = 0; i < AIT; i++){
            int fid = tid + i*256; int r = fid>>3, cq = fid&7;
            cpa16(as_sh + (uint32_t)(buf*ABUF + r*GA_STR + cq*4)*4,
                  &A[(size_t)(m0+r)*K + kt + cq*4]);
        }
#pragma unroll
        for (int i = 0; i < 2; i++){
            int fid = tid + i*256; int r = fid>>4, cq = fid&15;
            cpa16(bs_sh + (uint32_t)(buf*BBUF + r*GB_STR + cq*4)*4,
                  &Bm[(size_t)(kt+r)*Nn + n0 + cq*4]);
        }
        cp_commit();
    };

    issue(0, 0);
    int nt = K/32;
    for (int it = 0; it < nt; it++){
        int buf = it & 1;
        cp_wait<0>();
        __syncthreads();
        if (it + 1 < nt) issue((it+1)*32, buf^1);
#pragma unroll
        for (int ks = 0; ks < 4; ks++){
            int k0 = ks*8;
            uint32_t af[2][4];
#pragma unroll
            for (int mf = 0; mf < 2; mf++){
                int row = wm*32 + mf*16 + a_sub;
                ldsm4(af[mf], as_sh + (uint32_t)(buf*ABUF + row*GA_STR + k0 + a_kh)*4);
            }
#pragma unroll
            for (int nf = 0; nf < NFR; nf++){
                int col = wn*(64/WCOLS) + nf*8 + g;
                uint32_t b0 = Bs[buf*BBUF + (k0+t)*GB_STR + col];
                uint32_t b1 = Bs[buf*BBUF + (k0+4+t)*GB_STR + col];
                mma_tf32(acc[0][nf], af[0][0],af[0][1],af[0][2],af[0][3], b0,b1);
                mma_tf32(acc[1][nf], af[1][0],af[1][1],af[1][2],af[1][3], b0,b1);
            }
        }
        __syncthreads();
    }
#pragma unroll
    for (int mf = 0; mf < 2; mf++){
#pragma unroll
        for (int nf = 0; nf < NFR; nf++){
            int row = m0 + wm*32 + mf*16 + g;
            int col = n0 + wn*(64/WCOLS) + nf*8 + t*2;
            if (bias){
                float bx = bias[col], by = bias[col+1];
                *(float2*)&C[(size_t)row*Nn + col] =
                    make_float2(acc[mf][nf][0]+bx, acc[mf][nf][1]+by);
                *(float2*)&C[(size_t)(row+8)*Nn + col] =
                    make_float2(acc[mf][nf][2]+bx, acc[mf][nf][3]+by);
            } else {   // QKV path: round to tf32 for downstream attention
                *(uint2*)&C[(size_t)row*Nn + col] =
                    make_uint2(f2tf(acc[mf][nf][0]), f2tf(acc[mf][nf][1]));
                *(uint2*)&C[(size_t)(row+8)*Nn + col] =
                    make_uint2(f2tf(acc[mf][nf][2]), f2tf(acc[mf][nf][3]));
            }
        }
    }
}

// ---------------------------------------------------------------------------
// Flash attention, tf32 TC. 256 thr, 128 q-rows/CTA (warp owns 16 rows).
// qkv is pre-rounded tf32. K/V cp.async double-buffered. Q frags in regs.
// ---------------------------------------------------------------------------
#define AT_STR 68
#define V_STR  72
#define KBUF (64*AT_STR)
#define VBUF (64*V_STR)
#define ATTN_SMEM_WORDS (128*AT_STR + 2*KBUF + 2*VBUF)
#define ATTN_SMEM_BYTES (ATTN_SMEM_WORDS*4)   // 106496

__global__ __launch_bounds__(256, 2)
void attn_tc(const float* __restrict__ qkv, float* __restrict__ out){
    extern __shared__ uint32_t sm[];
    uint32_t* Ps = sm;                    // 128 x AT_STR : Q staging, then P
    uint32_t* Ks = sm + 128*AT_STR;       // 2 buffers
    uint32_t* Vs = Ks + 2*KBUF;           // 2 buffers

    int qt = blockIdx.x, bh = blockIdx.y; // qt: 0..7 (128-row tiles)
    int b = bh>>4, h = bh&15;
    int tid = threadIdx.x, w = tid>>5, lane = tid&31;
    int g = lane>>2, t = lane&3;
    const float* base = qkv + (size_t)b*NN*QKVN + h*DHEAD;

    uint32_t ps_sh = (uint32_t)__cvta_generic_to_shared(Ps);
    uint32_t ks_sh = (uint32_t)__cvta_generic_to_shared(Ks);
    uint32_t vs_sh = (uint32_t)__cvta_generic_to_shared(Vs);
    int a_row = w*16 + ((lane>>3)&1)*8 + (lane&7);
    uint32_t a_base = ps_sh + (uint32_t)(a_row*AT_STR + (lane>>4)*4)*4;
    int kb_row = ((lane>>4)<<3) + (lane&7);
    uint32_t kb_off = (uint32_t)(kb_row*AT_STR + ((lane>>3)&1)*4)*4;

    // Q staging (values already tf32; *0.125 is exact) -> frags in regs
#pragma unroll
    for (int i = 0; i < 8; i++){
        int fid = tid + i*256;
        int r = fid>>4, cq = fid&15;
        float4 v = *(const float4*)&base[(size_t)(qt*128+r)*QKVN + cq*4];
        *(uint4*)&Ps[r*AT_STR + cq*4] = make_uint4(
            __float_as_uint(v.x*0.125f), __float_as_uint(v.y*0.125f),
            __float_as_uint(v.z*0.125f), __float_as_uint(v.w*0.125f));
    }
    __syncthreads();
    uint32_t qf[8][4];
#pragma unroll
    for (int ks = 0; ks < 8; ks++)
        ldsm4(qf[ks], a_base + ks*32);

    auto issue = [&](int kt, int buf){
#pragma unroll
        for (int i = 0; i < 4; i++){
            int fid = tid + i*256;
            int r = fid>>4, cq = fid&15;
            const float* kr = &base[(size_t)(kt*64+r)*QKVN + INNER + cq*4];
            cpa16(ks_sh + (uint32_t)(buf*KBUF + r*AT_STR + cq*4)*4, kr);
            cpa16(vs_sh + (uint32_t)(buf*VBUF + r*V_STR  + cq*4)*4, kr + INNER);
        }
        cp_commit();
    };

    float o[8][4] = {};
    float mi0 = -INFINITY, mi1 = -INFINITY, li0 = 0.f, li1 = 0.f;

    issue(0, 0);
    for (int kt = 0; kt < 16; kt++){
        int buf = kt & 1;
        cp_wait<0>();
        __syncthreads();
        if (kt + 1 < 16) issue(kt+1, buf^1);

        // S = Q @ K^T
        float s[8][4] = {};
        uint32_t kbb = ks_sh + (uint32_t)(buf*KBUF)*4 + kb_off;
#pragma unroll
        for (int ks = 0; ks < 8; ks++){
            uint32_t* a = qf[ks];
#pragma unroll
            for (int nfp = 0; nfp < 4; nfp++){
                uint32_t kb[4];
                ldsm4(kb, kbb + (uint32_t)(nfp*16*AT_STR)*4 + ks*32);
                mma_tf32(s[2*nfp],   a[0],a[1],a[2],a[3], kb[0], kb[1]);
                mma_tf32(s[2*nfp+1], a[0],a[1],a[2],a[3], kb[2], kb[3]);
            }
        }

        // Online softmax (quad reduce over xor 1,2)
        float mx0 = -INFINITY, mx1 = -INFINITY;
#pragma unroll
        for (int nf = 0; nf < 8; nf++){
            mx0 = fmaxf(mx0, fmaxf(s[nf][0], s[nf][1]));
            mx1 = fmaxf(mx1, fmaxf(s[nf][2], s[nf][3]));
        }
        mx0 = fmaxf(mx0, __shfl_xor_sync(0xffffffffu, mx0, 1));
        mx0 = fmaxf(mx0, __shfl_xor_sync(0xffffffffu, mx0, 2));
        mx1 = fmaxf(mx1, __shfl_xor_sync(0xffffffffu, mx1, 1));
        mx1 = fmaxf(mx1, __shfl_xor_sync(0xffffffffu, mx1, 2));
        float mn0 = fmaxf(mi0, mx0), mn1 = fmaxf(mi1, mx1);
        float sc0 = __expf(mi0 - mn0), sc1 = __expf(mi1 - mn1);
        mi0 = mn0; mi1 = mn1;

        __syncwarp();      // prior PV reads of Ps done (warp-private rows)
        int prow = w*16 + g;
        float sum0 = 0.f, sum1 = 0.f;
#pragma unroll
        for (int nf = 0; nf < 8; nf++){
            float p0 = __expf(s[nf][0] - mn0), p1 = __expf(s[nf][1] - mn0);
            float p2 = __expf(s[nf][2] - mn1), p3 = __expf(s[nf][3] - mn1);
            sum0 += p0 + p1; sum1 += p2 + p3;
            int col = nf*8 + t*2;
            *(uint2*)&Ps[prow*AT_STR + col]     = make_uint2(f2tf(p0), f2tf(p1));
            *(uint2*)&Ps[(prow+8)*AT_STR + col] = make_uint2(f2tf(p2), f2tf(p3));
        }
        sum0 += __shfl_xor_sync(0xffffffffu, sum0, 1);
        sum0 += __shfl_xor_sync(0xffffffffu, sum0, 2);
        sum1 += __shfl_xor_sync(0xffffffffu, sum1, 1);
        sum1 += __shfl_xor_sync(0xffffffffu, sum1, 2);
        li0 = li0*sc0 + sum0;
        li1 = li1*sc1 + sum1;
#pragma unroll
        for (int nf = 0; nf < 8; nf++){
            o[nf][0] *= sc0; o[nf][1] *= sc0;
            o[nf][2] *= sc1; o[nf][3] *= sc1;
        }
        __syncwarp();

        // O += P @ V
#pragma unroll
        for (int ks = 0; ks < 8; ks++){
            int k0 = ks*8;
            uint32_t pa[4];
            ldsm4(pa, a_base + ks*32);
#pragma unroll
            for (int nf = 0; nf < 8; nf++){
                int d0 = nf*8 + g;
                uint32_t b0 = Vs[buf*VBUF + (k0+t)*V_STR + d0];
                uint32_t b1 = Vs[buf*VBUF + (k0+4+t)*V_STR + d0];
                mma_tf32(o[nf], pa[0],pa[1],pa[2],pa[3], b0, b1);
            }
        }
    }

    // Epilogue: tf32-round for the out-projection GEMM
    float inv0 = 1.f/li0, inv1 = 1.f/li1;
    int row = qt*128 + w*16 + g;
#pragma unroll
    for (int nf = 0; nf < 8; nf++){
        int col = h*DHEAD + nf*8 + t*2;
        *(uint2*)&out[((size_t)(b*NN+row))*INNER + col]   =
            make_uint2(f2tf(o[nf][0]*inv0), f2tf(o[nf][1]*inv0));
        *(uint2*)&out[((size_t)(b*NN+row+8))*INNER + col] =
            make_uint2(f2tf(o[nf][2]*inv1), f2tf(o[nf][3]*inv1));
    }
}

// ---------------------------------------------------------------------------
extern "C" void kernel_launch(void* const* d_in, const int* in_sizes, int n_in,
                              void* d_out, int out_size) {
    const float* x      = (const float*)d_in[0];
    const float* shift  = (const float*)d_in[1];
    const float* scale  = (const float*)d_in[2];
    const float* norm_w = (const float*)d_in[3];
    const float* norm_b = (const float*)d_in[4];
    const float* w_qkv  = (const float*)d_in[5];
    const float* w_out  = (const float*)d_in[6];
    const float* b_out  = (const float*)d_in[7];
    float* out = (float*)d_out;

    float *hp, *qkvp, *attnp, *wqp, *wop;
    cudaGetSymbolAddress((void**)&hp,    g_h);
    cudaGetSymbolAddress((void**)&qkvp,  g_qkv);
    cudaGetSymbolAddress((void**)&attnp, g_attn);
    cudaGetSymbolAddress((void**)&wqp,   g_wqkv);
    cudaGetSymbolAddress((void**)&wop,   g_wout);

    const int gsm128 = (2*128*GA_STR + 2*32*GB_STR)*4;   // 55296
    const int gsm64  = (2*64*GA_STR  + 2*32*GB_STR)*4;   // 36864
    cudaFuncSetAttribute(gemm_tc<128>,
                         cudaFuncAttributeMaxDynamicSharedMemorySize, gsm128);
    cudaFuncSetAttribute(gemm_tc<64>,
                         cudaFuncAttributeMaxDynamicSharedMemorySize, gsm64);
    cudaFuncSetAttribute(attn_tc,
                         cudaFuncAttributeMaxDynamicSharedMemorySize, ATTN_SMEM_BYTES);

    cvt_tf32_kernel<<<256, 256>>>(w_qkv, wqp, DIM*QKVN);
    cvt_tf32_kernel<<<128, 256>>>(w_out, wop, INNER*DIM);
    ln_mod_kernel<<<TOK/8, 256>>>(x, shift, scale, norm_w, norm_b);
    gemm_tc<128><<<dim3(QKVN/64, TOK/128), 256, gsm128>>>(hp, wqp, nullptr, qkvp,
                                                          TOK, QKVN, DIM);
    attn_tc<<<dim3(8, BB*HEADS), 256, ATTN_SMEM_BYTES>>>(qkvp, attnp);
    gemm_tc<64><<<dim3(DIM/64, TOK/64), 256, gsm64>>>(attnp, wop, b_out, out,
                                                      TOK, DIM, INNER);
}